// round 14
// baseline (speedup 1.0000x reference)
#include <cuda_runtime.h>
#include <cuda_bf16.h>
#include <cstdint>

#define HW   1024
#define CD   128
#define EPSF 1e-8f
#define STAGE_B 12288    // kc=16 stage: A_hi 4K | A_lo 4K | B_hi 2K | B_lo 2K

// Normalized features, bf16 hi/lo split, pixel-major:
// g_feat[view][p][0..127]=hi, [128..255]=lo   (512 B per pixel row)
__device__ __nv_bfloat16 g_feat[32 * HW * 256];

// ---------------------------------------------------------------------------
__device__ __forceinline__ uint32_t smem_u32(const void* p) {
    uint32_t a;
    asm("{ .reg .u64 t; cvta.to.shared.u64 t, %1; cvt.u32.u64 %0, t; }" : "=r"(a) : "l"(p));
    return a;
}

#define CP_ASYNC(s, g) \
    asm volatile("cp.async.cg.shared.global [%0], [%1], 16;" :: "r"(s), "l"(g))
#define CP_COMMIT() asm volatile("cp.async.commit_group;" ::: "memory")
#define CP_WAIT1()  asm volatile("cp.async.wait_group 1;" ::: "memory")

#define LDSM4(r, a) \
    asm volatile("ldmatrix.sync.aligned.m8n8.x4.shared.b16 {%0,%1,%2,%3}, [%4];" \
        : "=r"((r)[0]), "=r"((r)[1]), "=r"((r)[2]), "=r"((r)[3]) : "r"(a))

#define MMA(d, a, b0v, b1v)                                                  \
    asm volatile(                                                            \
        "mma.sync.aligned.m16n8k16.row.col.f32.bf16.bf16.f32 "               \
        "{%0,%1,%2,%3}, {%4,%5,%6,%7}, {%8,%9}, {%0,%1,%2,%3};\n"            \
        : "+f"((d)[0]), "+f"((d)[1]), "+f"((d)[2]), "+f"((d)[3])             \
        : "r"((a)[0]), "r"((a)[1]), "r"((a)[2]), "r"((a)[3]),                \
          "r"(b0v), "r"(b1v))

// 32B-row swizzle: chunk (16B) select XOR'd with row bit 2 -> any 8
// consecutive rows' chunks land on 8 distinct 16B bank groups.
#define SWZ(m, ch) ((uint32_t)((m) * 32 + (((ch) ^ (((m) >> 2) & 1)) << 4)))

// ---------------------------------------------------------------------------
// Kernel 1: L2-normalize per pixel, split to bf16 hi/lo, write pixel-major.
// 256 blocks x 128 threads (covers all SMs).
// ---------------------------------------------------------------------------
__global__ __launch_bounds__(128) void norm_split_kernel(const float* __restrict__ x) {
    __shared__ uint32_t tile[4][33 * 32];
    int w = threadIdx.x >> 5, l = threadIdx.x & 31;
    int gp = blockIdx.x * 128 + w * 32 + l;        // global pixel over 32 views
    int view = gp >> 10, p = gp & 1023;
    const float* xp = x + (size_t)view * (CD * HW) + p;

    float s = 0.f;
#pragma unroll 8
    for (int c = 0; c < CD; ++c) { float v = xp[c << 10]; s += v * v; }
    float inv = 1.f / (sqrtf(s) + EPSF);

    __nv_bfloat16* ob = g_feat + (size_t)(gp - l) * 256;   // warp's base pixel row

    for (int cb = 0; cb < 4; ++cb) {
#pragma unroll
        for (int ci = 0; ci < 32; ++ci) {
            float v = xp[(cb * 32 + ci) << 10] * inv;
            __nv_bfloat16 h = __float2bfloat16(v);
            __nv_bfloat16 lo = __float2bfloat16(v - __bfloat162float(h));
            tile[w][ci * 33 + l] = (uint32_t)__bfloat16_as_ushort(h)
                                 | ((uint32_t)__bfloat16_as_ushort(lo) << 16);
        }
        __syncwarp();
#pragma unroll
        for (int rr = 0; rr < 32; ++rr) {
            uint32_t v = tile[w][l * 33 + rr];
            __nv_bfloat16* row = ob + (size_t)rr * 256 + cb * 32 + l;
            row[0]   = __ushort_as_bfloat16((unsigned short)(v & 0xFFFF));
            row[128] = __ushort_as_bfloat16((unsigned short)(v >> 16));
        }
        __syncwarp();
    }
}

// ---------------------------------------------------------------------------
// Kernel 2: HMMA GEMM over 48 unique view pairs; CTA tile 128x64 (4 warps,
// warp 64x32). kc=16, THREE 12KB cp.async stages, wait_group 1 -> loads run
// two chunks ahead; the per-chunk __syncthreads is covered by prefetch slack.
// Epilogue (R10-proven): direct float2 stores to out[idx1]; transposed twin
// to out[idx2] via per-warp swizzled smem aliasing the dead stages.
// smem = 36KB -> 4 CTAs/SM, 16 warps, regs ~128.
// ---------------------------------------------------------------------------
__constant__ int c_pi[6] = {0, 0, 0, 1, 1, 2};
__constant__ int c_pj[6] = {1, 2, 3, 2, 3, 3};

__global__ __launch_bounds__(128, 4) void corr_gemm9(float* __restrict__ out) {
    extern __shared__ char smem[];
    uint32_t sb = smem_u32(smem);
    const int tid = threadIdx.x;
    const int w = tid >> 5, l = tid & 31;
    const int wm = w >> 1, wn = w & 1;          // warp grid 2x2
    const int lo16 = l & 15, hi2 = l >> 4;
    const int g = l >> 2, tg = l & 3;

    const int q0 = blockIdx.x * 64;
    const int p0 = blockIdx.y * 128;
    const int z  = blockIdx.z;                  // 0..47
    const int b  = z / 6, u = z % 6;
    const int i  = c_pi[u], j = c_pj[u];
    const int idx1 = b * 12 + i * 3 + (j - 1);
    const int idx2 = b * 12 + j * 3 + i;

    const char* Af = (const char*)g_feat + (size_t)(b * 4 + j) * HW * 512 + (size_t)p0 * 512;
    const char* Bf = (const char*)g_feat + (size_t)(b * 4 + i) * HW * 512 + (size_t)q0 * 512;

    float acc[4][4][4];
#pragma unroll
    for (int mt = 0; mt < 4; ++mt)
#pragma unroll
        for (int nt = 0; nt < 4; ++nt)
#pragma unroll
            for (int e = 0; e < 4; ++e) acc[mt][nt][e] = 0.f;

    // ---- stage loader: 768 16B chunks (A 512 + B 256), 6 per thread ----
    auto load_stage = [&](int kcg) {
        uint32_t sbase = sb + (uint32_t)(kcg % 3) * STAGE_B;
        const char* Ak = Af + kcg * 32;
        const char* Bk = Bf + kcg * 32;
#pragma unroll
        for (int it = 0; it < 4; ++it) {        // A region: m 0..127
            int u2 = it * 128 + tid;
            int m = u2 >> 2, half = (u2 >> 1) & 1, ch = u2 & 1;
            uint32_t soff = half * 4096u + SWZ(m, ch);
            CP_ASYNC(sbase + soff, Ak + (size_t)m * 512 + half * 256 + ch * 16);
        }
#pragma unroll
        for (int it = 0; it < 2; ++it) {        // B region: q 0..63
            int u2 = it * 128 + tid;
            int q = u2 >> 2, half = (u2 >> 1) & 1, ch = u2 & 1;
            uint32_t soff = 8192u + half * 2048u + SWZ(q, ch);
            CP_ASYNC(sbase + soff, Bk + (size_t)q * 512 + half * 256 + ch * 16);
        }
    };

    load_stage(0); CP_COMMIT();
    load_stage(1); CP_COMMIT();

    for (int s = 0; s < 8; ++s) {
        CP_WAIT1();                 // stage s resident (s+1 may still fly)
        __syncthreads();            // all warps: s visible, s-1 fully read
        if (s + 2 < 8) { load_stage(s + 2); CP_COMMIT(); }

        uint32_t st = sb + (uint32_t)(s % 3) * STAGE_B;

        uint32_t ah[4][4], al[4][4], bb[2][4], swb[2];
#pragma unroll
        for (int mt = 0; mt < 4; ++mt) {
            int m = wm * 64 + mt * 16 + lo16;
            uint32_t sw = SWZ(m, hi2);
            LDSM4(ah[mt], st + sw);             // A_hi
            LDSM4(al[mt], st + 4096 + sw);      // A_lo
        }
#pragma unroll
        for (int np = 0; np < 2; ++np) {
            int n = wn * 32 + np * 16 + lo16;
            swb[np] = SWZ(n, hi2);
            LDSM4(bb[np], st + 8192 + swb[np]); // B_hi
        }
#pragma unroll
        for (int mt = 0; mt < 4; ++mt)
#pragma unroll
            for (int nt = 0; nt < 4; ++nt)
                MMA(acc[mt][nt], ah[mt], bb[nt >> 1][nt & 1], bb[nt >> 1][2 + (nt & 1)]);
#pragma unroll
        for (int mt = 0; mt < 4; ++mt)
#pragma unroll
            for (int nt = 0; nt < 4; ++nt)
                MMA(acc[mt][nt], al[mt], bb[nt >> 1][nt & 1], bb[nt >> 1][2 + (nt & 1)]);
#pragma unroll
        for (int np = 0; np < 2; ++np)
            LDSM4(bb[np], st + 10240 + swb[np]); // B_lo
#pragma unroll
        for (int mt = 0; mt < 4; ++mt)
#pragma unroll
            for (int nt = 0; nt < 4; ++nt)
                MMA(acc[mt][nt], ah[mt], bb[nt >> 1][nt & 1], bb[nt >> 1][2 + (nt & 1)]);
    }

    // ---- epilogue 1: direct fp32 float2 stores to out[idx1] ----
    {
        float* op = out + (size_t)idx1 * (HW * HW);
#pragma unroll
        for (int mt = 0; mt < 4; ++mt) {
#pragma unroll
            for (int nt = 0; nt < 4; ++nt) {
                int row = p0 + wm * 64 + mt * 16 + g;
                int col = q0 + wn * 32 + nt * 8 + tg * 2;
                *(float2*)&op[(size_t)row * HW + col] =
                    make_float2(acc[mt][nt][0], acc[mt][nt][1]);
                *(float2*)&op[(size_t)(row + 8) * HW + col] =
                    make_float2(acc[mt][nt][2], acc[mt][nt][3]);
            }
        }
    }

    // ---- epilogue 2: transposed tile to out[idx2] via swizzled smem ----
    // tw aliases the (now dead) stage buffers -> sync before reuse
    __syncthreads();
    {
        float* tw = (float*)smem + w * 2048;   // per-warp 8KB: G[n][m], n<32, m<64
#pragma unroll
        for (int mt = 0; mt < 4; ++mt)
#pragma unroll
            for (int nt = 0; nt < 4; ++nt)
#pragma unroll
                for (int e = 0; e < 4; ++e) {
                    int n = nt * 8 + tg * 2 + (e & 1);
                    int m = mt * 16 + g + 8 * (e >> 1);
                    tw[n * 64 + (m ^ ((n & 6) << 2))] = acc[mt][nt][e];
                }
        __syncwarp();

        float* op = out + (size_t)idx2 * (HW * HW);
        const float2* tw2 = (const float2*)tw;
#pragma unroll
        for (int n = 0; n < 32; ++n) {
            float2 v = tw2[n * 32 + (l ^ ((n & 6) << 1))];   // (G[n][2l], G[n][2l+1])
            *(float2*)&op[(size_t)(q0 + wn * 32 + n) * HW + p0 + wm * 64 + 2 * l] = v;
        }
    }
}

// ---------------------------------------------------------------------------
extern "C" void kernel_launch(void* const* d_in, const int* in_sizes, int n_in,
                              void* d_out, int out_size) {
    const float* x = (const float*)d_in[0];
    float* out = (float*)d_out;

    norm_split_kernel<<<256, 128>>>(x);

    int smem_sz = 3 * STAGE_B;   // 36 KB
    cudaFuncSetAttribute(corr_gemm9, cudaFuncAttributeMaxDynamicSharedMemorySize, smem_sz);
    dim3 grid(16, 8, 48);
    corr_gemm9<<<grid, 128, smem_sz>>>(out);
}